// round 9
// baseline (speedup 1.0000x reference)
#include <cuda_runtime.h>
#include <cuda_bf16.h>
#include <cstdint>

// VanillaRNN via HMMA bf16-split (fp32 accum). B=256,T=1024,D=64,H=512,C=10.
// 128 CTAs = 16 clusters(8): cluster = 16-row tile, rank = 64-col slice.
// Handoff: h via L2 (STG/__ldcv) + remote mbarrier arrives (NO cluster.sync,
// NO atomics). 512 thr = 16 warps = 4 K-groups(144) x 4 col-groups(16).
// B-hi fragments register-resident across all steps.

#define T_SEQ  1024
#define B_DIM  256
#define D_IN   64
#define H_DIM  512
#define NCLS   10
#define KTOT   576
#define GRID   128
#define NTHR   512
#define TILE_R 16
#define TILE_C 64

#define PKB    1168            // A/B row stride bytes: 576*2 + 16 pad
#define REDW   70              // sRed row stride in floats (bank spread)

#define OFF_AH   0
#define OFF_AL   (OFF_AH + TILE_R * PKB)          // 18688
#define OFF_BH   (OFF_AL + TILE_R * PKB)          // 37376
#define OFF_BL   (OFF_BH + TILE_C * PKB)          // 112128
#define OFF_RED  (OFF_BL + TILE_C * PKB)          // 186880: 4*16*REDW fp32
#define OFF_BIAS (OFF_RED + 4 * 16 * REDW * 4)    // +17920 = 204800
#define OFF_MBAR (OFF_BIAS + 256)                 // 205056 (8B aligned)
#define SMEM_SZ  (OFF_MBAR + 16)

__device__ __nv_bfloat16 g_xhi[(size_t)B_DIM * T_SEQ * D_IN];
__device__ __nv_bfloat16 g_xlo[(size_t)B_DIM * T_SEQ * D_IN];
__device__ __nv_bfloat16 g_Hhi[2][B_DIM][H_DIM];
__device__ __nv_bfloat16 g_Hlo[2][B_DIM][H_DIM];
__device__ float         g_hfin[B_DIM][H_DIM];

__device__ __forceinline__ uint32_t smem_u32(const void* p) {
    uint32_t a;
    asm("{ .reg .u64 t; cvta.to.shared.u64 t, %1; cvt.u32.u64 %0, t; }"
        : "=r"(a) : "l"(p));
    return a;
}

#define LDSM4(r0, r1, r2, r3, addr)                                        \
    asm volatile("ldmatrix.sync.aligned.m8n8.x4.shared.b16 "               \
                 "{%0,%1,%2,%3}, [%4];"                                    \
                 : "=r"(r0), "=r"(r1), "=r"(r2), "=r"(r3) : "r"(addr))
#define MMA16816(d, a0, a1, a2, a3, b0, b1)                                \
    asm volatile("mma.sync.aligned.m16n8k16.row.col.f32.bf16.bf16.f32 "    \
                 "{%0,%1,%2,%3}, {%4,%5,%6,%7}, {%8,%9}, {%0,%1,%2,%3};"   \
                 : "+f"(d[0]), "+f"(d[1]), "+f"(d[2]), "+f"(d[3])          \
                 : "r"(a0), "r"(a1), "r"(a2), "r"(a3), "r"(b0), "r"(b1))

__device__ __forceinline__ void mbar_arrive_rank(uint32_t mbar_local,
                                                 uint32_t rank) {
    asm volatile(
        "{\n\t.reg .b32 ra;\n\t"
        "mapa.shared::cluster.u32 ra, %0, %1;\n\t"
        "mbarrier.arrive.shared::cluster.b64 _, [ra];\n\t}"
        :: "r"(mbar_local), "r"(rank) : "memory");
}
__device__ __forceinline__ void mbar_wait(uint32_t a, uint32_t parity) {
    asm volatile(
        "{\n\t.reg .pred P1;\n\t"
        "W_%=:\n\t"
        "mbarrier.try_wait.parity.shared::cta.b64 P1, [%0], %1, 0x989680;\n\t"
        "@P1 bra.uni D_%=;\n\t"
        "bra.uni W_%=;\n\t"
        "D_%=:\n\t}"
        :: "r"(a), "r"(parity) : "memory");
}

__global__ void __cluster_dims__(8, 1, 1) __launch_bounds__(NTHR, 1)
rnn_hmma_mb_kernel(const float* __restrict__ x,
                   const float* __restrict__ Whx,
                   const float* __restrict__ Whh,
                   const float* __restrict__ Wph,
                   const float* __restrict__ bh,
                   const float* __restrict__ bp,
                   float* __restrict__ out)
{
    extern __shared__ __align__(16) char smg[];
    const uint32_t sb = smem_u32(smg);

    const int tid  = threadIdx.x;
    const int wid  = tid >> 5;
    const int lane = tid & 31;
    const int bid  = blockIdx.x;
    const int jt   = bid & 7;            // col slice == cluster rank
    const int it   = bid >> 3;           // row tile
    const int c0   = jt * TILE_C;
    const int r0   = it * TILE_R;

    float* sBias = reinterpret_cast<float*>(smg + OFF_BIAS);
    float* sRed  = reinterpret_cast<float*>(smg + OFF_RED);
    const uint32_t mbar = sb + OFF_MBAR;

    // ---- init mbarrier (8 arrivals per phase) ----
    if (tid == 0) {
        asm volatile("mbarrier.init.shared.b64 [%0], %1;"
                     :: "r"(mbar), "r"(8u) : "memory");
    }

    // ---- one-time: W slice -> SMEM bf16 hi/lo, padded rows [n][k] ----
    for (int i = tid; i < TILE_C * KTOT; i += NTHR) {
        const int n = i / KTOT, k = i - n * KTOT;
        const float w = (k < D_IN) ? Whx[k * H_DIM + c0 + n]
                                   : Whh[(k - D_IN) * H_DIM + c0 + n];
        const __nv_bfloat16 h16 = __float2bfloat16(w);
        const __nv_bfloat16 l16 = __float2bfloat16(w - __bfloat162float(h16));
        *reinterpret_cast<__nv_bfloat16*>(smg + OFF_BH + n * PKB + k * 2) = h16;
        *reinterpret_cast<__nv_bfloat16*>(smg + OFF_BL + n * PKB + k * 2) = l16;
    }
    if (tid < TILE_C) sBias[tid] = bh[c0 + tid];

    // ---- prologue: split THIS row-tile's x rows into bf16 hi/lo ----
    {
        const size_t gbase = (size_t)r0 * T_SEQ * D_IN / 4;   // float4 units
        const int    total = TILE_R * T_SEQ * D_IN / 4;
        for (int i = jt * NTHR + tid; i < total; i += 8 * NTHR) {
            const float4 v = __ldg(reinterpret_cast<const float4*>(x) + gbase + i);
            const __nv_bfloat162 hA = __floats2bfloat162_rn(v.x, v.y);
            const __nv_bfloat162 hB = __floats2bfloat162_rn(v.z, v.w);
            const __nv_bfloat162 lA = __floats2bfloat162_rn(
                v.x - __bfloat162float(hA.x), v.y - __bfloat162float(hA.y));
            const __nv_bfloat162 lB = __floats2bfloat162_rn(
                v.z - __bfloat162float(hB.x), v.w - __bfloat162float(hB.y));
            const size_t o = gbase + i;
            reinterpret_cast<__nv_bfloat162*>(g_xhi)[2 * o]     = hA;
            reinterpret_cast<__nv_bfloat162*>(g_xhi)[2 * o + 1] = hB;
            reinterpret_cast<__nv_bfloat162*>(g_xlo)[2 * o]     = lA;
            reinterpret_cast<__nv_bfloat162*>(g_xlo)[2 * o + 1] = lB;
        }
    }
    __syncthreads();
    __threadfence();     // x split visible gpu-wide before cluster release
    // one-time cluster sync: mbar init + x split visible to all 8 ranks
    asm volatile("barrier.cluster.arrive.aligned;" ::: "memory");
    asm volatile("barrier.cluster.wait.aligned;" ::: "memory");

    // warp roles: kg = K-group (144 each), ng = 16-col group
    const int kg = wid >> 2;
    const int ng = wid & 3;
    const int kbase = kg * 144;

    const uint32_t aoff = (uint32_t)(lane & 15) * PKB
                        + (uint32_t)((lane >> 4) << 4)
                        + (uint32_t)kbase * 2;
    const uint32_t boff = (uint32_t)(ng * 16 + ((lane >> 4) << 3) + (lane & 7)) * PKB
                        + (uint32_t)(((lane >> 3) & 1) << 4)
                        + (uint32_t)kbase * 2;

    const uint32_t sAh = sb + OFF_AH, sAl = sb + OFF_AL;
    const uint32_t sBh = sb + OFF_BH, sBl = sb + OFF_BL;

    // ---- B-hi fragments: load ONCE, keep in registers for all 1024 steps ----
    uint32_t bhr[9][4];
    #pragma unroll
    for (int s = 0; s < 9; ++s)
        LDSM4(bhr[s][0], bhr[s][1], bhr[s][2], bhr[s][3],
              sBh + boff + (uint32_t)s * 32);

    const int erow = (tid * 2) >> 6;
    const int ecol = (tid * 2) & 63;

    // ---- stage A for t=0: x_0 + h_0 (global zeros) ----
    for (int u = tid; u < 256; u += NTHR) {
        const int half = u >> 7, uu = u & 127, r = uu >> 3, q = uu & 7;
        const __nv_bfloat16* src = (half ? g_xlo : g_xhi)
            + ((size_t)(r0 + r) * T_SEQ + 0) * D_IN + q * 8;
        *reinterpret_cast<uint4*>(smg + (half ? OFF_AL : OFF_AH) + r * PKB + q * 16)
            = __ldg(reinterpret_cast<const uint4*>(src));
    }
    for (int u = tid; u < 2048; u += NTHR) {
        const int half = u >> 10, uu = u & 1023, r = uu >> 6, q = uu & 63;
        const __nv_bfloat16* src =
            (half ? &g_Hlo[0][0][0] : &g_Hhi[0][0][0])
            + (size_t)(r0 + r) * H_DIM + q * 8;
        *reinterpret_cast<uint4*>(smg + (half ? OFF_AL : OFF_AH)
                                  + r * PKB + (8 + q) * 16)
            = __ldcv(reinterpret_cast<const uint4*>(src));
    }

    for (int t = 0; t < T_SEQ; ++t) {
        __syncthreads();   // A staged

        // ---- warp GEMM: m16 x n16 x k144, 3-product bf16 split ----
        float acc[2][4] = {};
        #pragma unroll
        for (int s = 0; s < 9; ++s) {
            const uint32_t ka = (uint32_t)s * 32;
            uint32_t ah0, ah1, ah2, ah3, al0, al1, al2, al3;
            uint32_t bl0, bl1, bl2, bl3;
            LDSM4(ah0, ah1, ah2, ah3, sAh + aoff + ka);
            LDSM4(al0, al1, al2, al3, sAl + aoff + ka);
            LDSM4(bl0, bl1, bl2, bl3, sBl + boff + ka);
            MMA16816(acc[0], ah0, ah1, ah2, ah3, bhr[s][0], bhr[s][1]);
            MMA16816(acc[0], al0, al1, al2, al3, bhr[s][0], bhr[s][1]);
            MMA16816(acc[0], ah0, ah1, ah2, ah3, bl0, bl1);
            MMA16816(acc[1], ah0, ah1, ah2, ah3, bhr[s][2], bhr[s][3]);
            MMA16816(acc[1], al0, al1, al2, al3, bhr[s][2], bhr[s][3]);
            MMA16816(acc[1], ah0, ah1, ah2, ah3, bl2, bl3);
        }

        // ---- split-K partials -> sRed[kg][16][REDW] (conflict-spread) ----
        {
            float* rb = sRed + kg * (16 * REDW);
            const int gr0 = lane >> 2;
            #pragma unroll
            for (int g = 0; g < 2; ++g) {
                const int c = ng * 16 + g * 8 + (lane & 3) * 2;
                *reinterpret_cast<float2*>(rb + gr0 * REDW + c) =
                    make_float2(acc[g][0], acc[g][1]);
                *reinterpret_cast<float2*>(rb + (gr0 + 8) * REDW + c) =
                    make_float2(acc[g][2], acc[g][3]);
            }
        }
        __syncthreads();

        // ---- reduce + bias + tanh -> h bf16 hi/lo -> global ----
        {
            const int base = erow * REDW + ecol;
            float2 p0 = *reinterpret_cast<float2*>(sRed + base);
            float2 p1 = *reinterpret_cast<float2*>(sRed + 16 * REDW + base);
            float2 p2 = *reinterpret_cast<float2*>(sRed + 32 * REDW + base);
            float2 p3 = *reinterpret_cast<float2*>(sRed + 48 * REDW + base);
            const float v0 = tanhf((p0.x + p1.x) + (p2.x + p3.x) + sBias[ecol]);
            const float v1 = tanhf((p0.y + p1.y) + (p2.y + p3.y) + sBias[ecol + 1]);

            const __nv_bfloat162 h01 = __floats2bfloat162_rn(v0, v1);
            const __nv_bfloat162 l01 = __floats2bfloat162_rn(
                v0 - __bfloat162float(h01.x), v1 - __bfloat162float(h01.y));

            const int row = r0 + erow, col = c0 + ecol;
            *reinterpret_cast<uint32_t*>(&g_Hhi[(t + 1) & 1][row][col]) =
                *reinterpret_cast<const uint32_t*>(&h01);
            *reinterpret_cast<uint32_t*>(&g_Hlo[(t + 1) & 1][row][col]) =
                *reinterpret_cast<const uint32_t*>(&l01);
            if (t == T_SEQ - 1)
                *reinterpret_cast<float2*>(&g_hfin[row][col]) =
                    make_float2(v0, v1);
        }

        // ---- handoff: release h stores, remote arrives, overlap x-stage ----
        __syncthreads();                 // all h STGs issued
        if (tid < 8) {
            __threadfence();             // release chain (sync -> fence.gpu)
            mbar_arrive_rank(mbar, (uint32_t)tid);
        }
        if (t + 1 < T_SEQ) {
            for (int u = tid; u < 256; u += NTHR) {
                const int half = u >> 7, uu = u & 127, r = uu >> 3, q = uu & 7;
                const __nv_bfloat16* src = (half ? g_xlo : g_xhi)
                    + ((size_t)(r0 + r) * T_SEQ + (t + 1)) * D_IN + q * 8;
                *reinterpret_cast<uint4*>(smg + (half ? OFF_AL : OFF_AH)
                                          + r * PKB + q * 16)
                    = __ldg(reinterpret_cast<const uint4*>(src));
            }
        }
        mbar_wait(mbar, (uint32_t)(t & 1));
        __threadfence();                 // acquire for the global h reads

        if (t + 1 < T_SEQ) {
            const __nv_bfloat16* hbh = &g_Hhi[(t + 1) & 1][0][0];
            const __nv_bfloat16* hbl = &g_Hlo[(t + 1) & 1][0][0];
            for (int u = tid; u < 2048; u += NTHR) {
                const int half = u >> 10, uu = u & 1023, r = uu >> 6, q = uu & 63;
                const __nv_bfloat16* src = (half ? hbl : hbh)
                    + (size_t)(r0 + r) * H_DIM + q * 8;
                *reinterpret_cast<uint4*>(smg + (half ? OFF_AL : OFF_AH)
                                          + r * PKB + (8 + q) * 16)
                    = __ldcv(reinterpret_cast<const uint4*>(src));
            }
        }
    }

    // ---- final projection p = h_final @ Wph + bp (rank-0 CTAs) ----
    if (jt == 0) {
        float* sW = reinterpret_cast<float*>(smg + OFF_BH);   // 5120 floats
        float* sH = reinterpret_cast<float*>(smg + OFF_AH);   // 16x512
        for (int i = tid; i < H_DIM * NCLS; i += NTHR)
            sW[i] = Wph[i];
        for (int i = tid; i < TILE_R * H_DIM; i += NTHR) {
            const int r = i >> 9, k = i & 511;
            sH[r * H_DIM + k] = __ldcv(&g_hfin[r0 + r][k]);
        }
        __syncthreads();
        for (int i = tid; i < TILE_R * NCLS; i += NTHR) {
            const int r = i / NCLS, cc = i - (i / NCLS) * NCLS;
            float s = bp[cc];
            const float* hr = sH + r * H_DIM;
            #pragma unroll 8
            for (int k = 0; k < H_DIM; ++k)
                s += hr[k] * sW[k * NCLS + cc];
            out[(r0 + r) * NCLS + cc] = s;
        }
    }
}

extern "C" void kernel_launch(void* const* d_in, const int* in_sizes, int n_in,
                              void* d_out, int out_size)
{
    const float* x   = (const float*)d_in[0];
    const float* Whx = (const float*)d_in[1];
    const float* Whh = (const float*)d_in[2];
    const float* Wph = (const float*)d_in[3];
    const float* bh  = (const float*)d_in[4];
    const float* bp  = (const float*)d_in[5];
    float* out = (float*)d_out;

    // Deterministic per-launch state: zero h_0 (buffer 0, hi+lo).
    void *hhi_a = nullptr, *hlo_a = nullptr;
    cudaGetSymbolAddress(&hhi_a, g_Hhi);
    cudaGetSymbolAddress(&hlo_a, g_Hlo);
    cudaMemsetAsync(hhi_a, 0, (size_t)B_DIM * H_DIM * sizeof(__nv_bfloat16));
    cudaMemsetAsync(hlo_a, 0, (size_t)B_DIM * H_DIM * sizeof(__nv_bfloat16));

    cudaFuncSetAttribute(rnn_hmma_mb_kernel,
                         cudaFuncAttributeMaxDynamicSharedMemorySize, SMEM_SZ);

    rnn_hmma_mb_kernel<<<GRID, NTHR, SMEM_SZ>>>(x, Whx, Whh, Wph, bh, bp, out);
}

// round 10
// speedup vs baseline: 1.8198x; 1.8198x over previous
#include <cuda_runtime.h>
#include <cuda_bf16.h>
#include <cstdint>

// VanillaRNN via HMMA bf16-split (fp32 accum). B=256,T=1024,D=64,H=512,C=10.
// 128 CTAs = 16 row-tiles(16 rows) x 8 col-slices(64 cols), 512 threads.
// Sync: per-row-tile atomic counter barrier (R8-proven; clusters lose).
// Warps: 4 K-groups(144) x 4 col-groups(16); 3-product bf16-split MMA.
// R10: conflict-free sRed (stride 70), B-hi register-resident, MLP-shaped
// staging (x LDG before reduce, h staged with 4 unrolled __ldcv).

#define T_SEQ  1024
#define B_DIM  256
#define D_IN   64
#define H_DIM  512
#define NCLS   10
#define KTOT   576
#define GRID   128
#define NTHR   512
#define TILE_R 16
#define TILE_C 64

#define PKB    1168            // A/B row stride bytes: 576*2 + 16 pad
#define REDW   70              // sRed row stride in floats (bank spread)

#define OFF_AH   0
#define OFF_AL   (OFF_AH + TILE_R * PKB)          // 18688
#define OFF_BH   (OFF_AL + TILE_R * PKB)          // 37376
#define OFF_BL   (OFF_BH + TILE_C * PKB)          // 112128
#define OFF_RED  (OFF_BL + TILE_C * PKB)          // 186880
#define OFF_BIAS (OFF_RED + 4 * 16 * REDW * 4)    // 186880+17920 = 204800
#define SMEM_SZ  (OFF_BIAS + 256 + 16)

__device__ __nv_bfloat16 g_xhi[(size_t)B_DIM * T_SEQ * D_IN];
__device__ __nv_bfloat16 g_xlo[(size_t)B_DIM * T_SEQ * D_IN];
__device__ __nv_bfloat16 g_Hhi[2][B_DIM][H_DIM];
__device__ __nv_bfloat16 g_Hlo[2][B_DIM][H_DIM];
__device__ float         g_hfin[B_DIM][H_DIM];
__device__ unsigned      g_bar[16 * 32];   // 1 counter per row-tile, 128B apart

__device__ __forceinline__ uint32_t smem_u32(const void* p) {
    uint32_t a;
    asm("{ .reg .u64 t; cvta.to.shared.u64 t, %1; cvt.u32.u64 %0, t; }"
        : "=r"(a) : "l"(p));
    return a;
}

#define LDSM4(r0, r1, r2, r3, addr)                                        \
    asm volatile("ldmatrix.sync.aligned.m8n8.x4.shared.b16 "               \
                 "{%0,%1,%2,%3}, [%4];"                                    \
                 : "=r"(r0), "=r"(r1), "=r"(r2), "=r"(r3) : "r"(addr))
#define MMA16816(d, a0, a1, a2, a3, b0, b1)                                \
    asm volatile("mma.sync.aligned.m16n8k16.row.col.f32.bf16.bf16.f32 "    \
                 "{%0,%1,%2,%3}, {%4,%5,%6,%7}, {%8,%9}, {%0,%1,%2,%3};"   \
                 : "+f"(d[0]), "+f"(d[1]), "+f"(d[2]), "+f"(d[3])          \
                 : "r"(a0), "r"(a1), "r"(a2), "r"(a3), "r"(b0), "r"(b1))

// Per-row-tile barrier: 8 CTAs arrive on a private counter; tid0 polls.
__device__ __forceinline__ void tile_barrier(int tid, int it, unsigned epoch) {
    __threadfence();
    __syncthreads();
    if (tid == 0) {
        atomicAdd(&g_bar[it * 32], 1u);
        while (*(volatile unsigned*)&g_bar[it * 32] < epoch * 8u) { }
        __threadfence();
    }
    __syncthreads();
}

__global__ void __launch_bounds__(NTHR, 1)
rnn_hmma10_kernel(const float* __restrict__ x,
                  const float* __restrict__ Whx,
                  const float* __restrict__ Whh,
                  const float* __restrict__ Wph,
                  const float* __restrict__ bh,
                  const float* __restrict__ bp,
                  float* __restrict__ out)
{
    extern __shared__ __align__(16) char smg[];
    const uint32_t sb = smem_u32(smg);

    const int tid  = threadIdx.x;
    const int wid  = tid >> 5;
    const int lane = tid & 31;
    const int bid  = blockIdx.x;
    const int jt   = bid & 7;            // col slice
    const int it   = bid >> 3;           // row tile
    const int c0   = jt * TILE_C;
    const int r0   = it * TILE_R;

    float* sBias = reinterpret_cast<float*>(smg + OFF_BIAS);
    float* sRed  = reinterpret_cast<float*>(smg + OFF_RED);

    // ---- one-time: W slice -> SMEM bf16 hi/lo, padded rows [n][k] ----
    for (int i = tid; i < TILE_C * KTOT; i += NTHR) {
        const int n = i / KTOT, k = i - n * KTOT;
        const float w = (k < D_IN) ? Whx[k * H_DIM + c0 + n]
                                   : Whh[(k - D_IN) * H_DIM + c0 + n];
        const __nv_bfloat16 h16 = __float2bfloat16(w);
        const __nv_bfloat16 l16 = __float2bfloat16(w - __bfloat162float(h16));
        *reinterpret_cast<__nv_bfloat16*>(smg + OFF_BH + n * PKB + k * 2) = h16;
        *reinterpret_cast<__nv_bfloat16*>(smg + OFF_BL + n * PKB + k * 2) = l16;
    }
    if (tid < TILE_C) sBias[tid] = bh[c0 + tid];

    // ---- prologue: split THIS row-tile's x rows into bf16 hi/lo ----
    {
        const size_t gbase = (size_t)r0 * T_SEQ * D_IN / 4;   // float4 units
        const int    total = TILE_R * T_SEQ * D_IN / 4;
        for (int i = jt * NTHR + tid; i < total; i += 8 * NTHR) {
            const float4 v = __ldg(reinterpret_cast<const float4*>(x) + gbase + i);
            const __nv_bfloat162 hA = __floats2bfloat162_rn(v.x, v.y);
            const __nv_bfloat162 hB = __floats2bfloat162_rn(v.z, v.w);
            const __nv_bfloat162 lA = __floats2bfloat162_rn(
                v.x - __bfloat162float(hA.x), v.y - __bfloat162float(hA.y));
            const __nv_bfloat162 lB = __floats2bfloat162_rn(
                v.z - __bfloat162float(hB.x), v.w - __bfloat162float(hB.y));
            const size_t o = gbase + i;
            reinterpret_cast<__nv_bfloat162*>(g_xhi)[2 * o]     = hA;
            reinterpret_cast<__nv_bfloat162*>(g_xhi)[2 * o + 1] = hB;
            reinterpret_cast<__nv_bfloat162*>(g_xlo)[2 * o]     = lA;
            reinterpret_cast<__nv_bfloat162*>(g_xlo)[2 * o + 1] = lB;
        }
    }
    __syncthreads();
    tile_barrier(tid, it, 1);

    // warp roles: kg = K-group (144 each), ng = 16-col group
    const int kg = wid >> 2;
    const int ng = wid & 3;
    const int kbase = kg * 144;

    const uint32_t aoff = (uint32_t)(lane & 15) * PKB
                        + (uint32_t)((lane >> 4) << 4)
                        + (uint32_t)kbase * 2;
    const uint32_t boff = (uint32_t)(ng * 16 + ((lane >> 4) << 3) + (lane & 7)) * PKB
                        + (uint32_t)(((lane >> 3) & 1) << 4)
                        + (uint32_t)kbase * 2;

    const uint32_t sAh = sb + OFF_AH, sAl = sb + OFF_AL;
    const uint32_t sBh = sb + OFF_BH, sBl = sb + OFF_BL;

    // ---- B-hi fragments: load ONCE, register-resident all 1024 steps ----
    uint32_t bhr[9][4];
    #pragma unroll
    for (int s = 0; s < 9; ++s)
        LDSM4(bhr[s][0], bhr[s][1], bhr[s][2], bhr[s][3],
              sBh + boff + (uint32_t)s * 32);

    const int erow = (tid * 2) >> 6;
    const int ecol = (tid * 2) & 63;

    // x-stage mapping (tid < 256 handles one uint4)
    const int xhalf = tid >> 7;          // valid when tid<256
    const int xr    = (tid & 127) >> 3;
    const int xq    = tid & 7;

    // h-stage mapping: 4 units per thread, u = tid + 512*j
    // j=0,1 -> hi half; j=2,3 -> lo half
    const int hr0 = tid >> 6,            hq0 = tid & 63;          // u=tid
    const int hr1 = (tid + 512) >> 6 & 15, hq1 = (tid + 512) & 63; // u=tid+512

    // ---- stage A for t=0: x_0 + h_0 (global zeros) ----
    if (tid < 256) {
        const __nv_bfloat16* src = (xhalf ? g_xlo : g_xhi)
            + ((size_t)(r0 + xr) * T_SEQ + 0) * D_IN + xq * 8;
        *reinterpret_cast<uint4*>(smg + (xhalf ? OFF_AL : OFF_AH)
                                  + xr * PKB + xq * 16)
            = __ldg(reinterpret_cast<const uint4*>(src));
    }
    for (int u = tid; u < 2048; u += NTHR) {
        const int half = u >> 10, uu = u & 1023, r = uu >> 6, q = uu & 63;
        const __nv_bfloat16* src =
            (half ? &g_Hlo[0][0][0] : &g_Hhi[0][0][0])
            + (size_t)(r0 + r) * H_DIM + q * 8;
        *reinterpret_cast<uint4*>(smg + (half ? OFF_AL : OFF_AH)
                                  + r * PKB + (8 + q) * 16)
            = __ldcv(reinterpret_cast<const uint4*>(src));
    }

    for (int t = 0; t < T_SEQ; ++t) {
        __syncthreads();   // A staged

        // ---- warp GEMM: m16 x n16 x k144, 3-product bf16 split ----
        float acc[2][4] = {};
        #pragma unroll
        for (int s = 0; s < 9; ++s) {
            const uint32_t ka = (uint32_t)s * 32;
            uint32_t ah0, ah1, ah2, ah3, al0, al1, al2, al3;
            uint32_t bl0, bl1, bl2, bl3;
            LDSM4(ah0, ah1, ah2, ah3, sAh + aoff + ka);
            LDSM4(al0, al1, al2, al3, sAl + aoff + ka);
            LDSM4(bl0, bl1, bl2, bl3, sBl + boff + ka);
            MMA16816(acc[0], ah0, ah1, ah2, ah3, bhr[s][0], bhr[s][1]);
            MMA16816(acc[0], al0, al1, al2, al3, bhr[s][0], bhr[s][1]);
            MMA16816(acc[0], ah0, ah1, ah2, ah3, bl0, bl1);
            MMA16816(acc[1], ah0, ah1, ah2, ah3, bhr[s][2], bhr[s][3]);
            MMA16816(acc[1], al0, al1, al2, al3, bhr[s][2], bhr[s][3]);
            MMA16816(acc[1], ah0, ah1, ah2, ah3, bl2, bl3);
        }

        // ---- split-K partials -> sRed[kg][16][REDW] (bank-spread) ----
        {
            float* rb = sRed + kg * (16 * REDW);
            const int gr0 = lane >> 2;
            #pragma unroll
            for (int g = 0; g < 2; ++g) {
                const int c = ng * 16 + g * 8 + (lane & 3) * 2;
                *reinterpret_cast<float2*>(rb + gr0 * REDW + c) =
                    make_float2(acc[g][0], acc[g][1]);
                *reinterpret_cast<float2*>(rb + (gr0 + 8) * REDW + c) =
                    make_float2(acc[g][2], acc[g][3]);
            }
        }
        __syncthreads();

        // ---- issue x_{t+1} LDG first (flies over the reduce) ----
        uint4 xv;
        const bool do_x = (t + 1 < T_SEQ) && (tid < 256);
        if (do_x) {
            const __nv_bfloat16* src = (xhalf ? g_xlo : g_xhi)
                + ((size_t)(r0 + xr) * T_SEQ + (t + 1)) * D_IN + xq * 8;
            xv = __ldg(reinterpret_cast<const uint4*>(src));
        }

        // ---- reduce + bias + tanh -> h bf16 hi/lo -> global ----
        {
            const int base = erow * REDW + ecol;
            float2 p0 = *reinterpret_cast<float2*>(sRed + base);
            float2 p1 = *reinterpret_cast<float2*>(sRed + 16 * REDW + base);
            float2 p2 = *reinterpret_cast<float2*>(sRed + 32 * REDW + base);
            float2 p3 = *reinterpret_cast<float2*>(sRed + 48 * REDW + base);
            const float v0 = tanhf((p0.x + p1.x) + (p2.x + p3.x) + sBias[ecol]);
            const float v1 = tanhf((p0.y + p1.y) + (p2.y + p3.y) + sBias[ecol + 1]);

            const __nv_bfloat162 h01 = __floats2bfloat162_rn(v0, v1);
            const __nv_bfloat162 l01 = __floats2bfloat162_rn(
                v0 - __bfloat162float(h01.x), v1 - __bfloat162float(h01.y));

            const int row = r0 + erow, col = c0 + ecol;
            *reinterpret_cast<uint32_t*>(&g_Hhi[(t + 1) & 1][row][col]) =
                *reinterpret_cast<const uint32_t*>(&h01);
            *reinterpret_cast<uint32_t*>(&g_Hlo[(t + 1) & 1][row][col]) =
                *reinterpret_cast<const uint32_t*>(&l01);
            if (t == T_SEQ - 1)
                *reinterpret_cast<float2*>(&g_hfin[row][col]) =
                    make_float2(v0, v1);
        }

        // ---- land x_{t+1} into SMEM (A reads finished at last sync) ----
        if (do_x) {
            *reinterpret_cast<uint4*>(smg + (xhalf ? OFF_AL : OFF_AH)
                                      + xr * PKB + xq * 16) = xv;
        }

        // ---- per-row-tile barrier, then stage h_{t+1} (MLP=4) ----
        tile_barrier(tid, it, (unsigned)(t + 2));

        if (t + 1 < T_SEQ) {
            const __nv_bfloat16* hbh = &g_Hhi[(t + 1) & 1][0][0];
            const __nv_bfloat16* hbl = &g_Hlo[(t + 1) & 1][0][0];
            // 4 independent loads, then 4 stores
            const uint4 v0 = __ldcv(reinterpret_cast<const uint4*>(
                hbh + (size_t)(r0 + hr0) * H_DIM + hq0 * 8));
            const uint4 v1 = __ldcv(reinterpret_cast<const uint4*>(
                hbh + (size_t)(r0 + hr1) * H_DIM + hq1 * 8));
            const uint4 v2 = __ldcv(reinterpret_cast<const uint4*>(
                hbl + (size_t)(r0 + hr0) * H_DIM + hq0 * 8));
            const uint4 v3 = __ldcv(reinterpret_cast<const uint4*>(
                hbl + (size_t)(r0 + hr1) * H_DIM + hq1 * 8));
            *reinterpret_cast<uint4*>(smg + OFF_AH + hr0 * PKB + (8 + hq0) * 16) = v0;
            *reinterpret_cast<uint4*>(smg + OFF_AH + hr1 * PKB + (8 + hq1) * 16) = v1;
            *reinterpret_cast<uint4*>(smg + OFF_AL + hr0 * PKB + (8 + hq0) * 16) = v2;
            *reinterpret_cast<uint4*>(smg + OFF_AL + hr1 * PKB + (8 + hq1) * 16) = v3;
        }
    }

    // ---- final projection p = h_final @ Wph + bp (col-slice-0 CTAs) ----
    if (jt == 0) {
        float* sW = reinterpret_cast<float*>(smg + OFF_BH);   // 5120 floats
        float* sH = reinterpret_cast<float*>(smg + OFF_AH);   // 16x512
        for (int i = tid; i < H_DIM * NCLS; i += NTHR)
            sW[i] = Wph[i];
        for (int i = tid; i < TILE_R * H_DIM; i += NTHR) {
            const int r = i >> 9, k = i & 511;
            sH[r * H_DIM + k] = __ldcv(&g_hfin[r0 + r][k]);
        }
        __syncthreads();
        for (int i = tid; i < TILE_R * NCLS; i += NTHR) {
            const int r = i / NCLS, cc = i - (i / NCLS) * NCLS;
            float s = bp[cc];
            const float* hr = sH + r * H_DIM;
            #pragma unroll 8
            for (int k = 0; k < H_DIM; ++k)
                s += hr[k] * sW[k * NCLS + cc];
            out[(r0 + r) * NCLS + cc] = s;
        }
    }
}

extern "C" void kernel_launch(void* const* d_in, const int* in_sizes, int n_in,
                              void* d_out, int out_size)
{
    const float* x   = (const float*)d_in[0];
    const float* Whx = (const float*)d_in[1];
    const float* Whh = (const float*)d_in[2];
    const float* Wph = (const float*)d_in[3];
    const float* bh  = (const float*)d_in[4];
    const float* bp  = (const float*)d_in[5];
    float* out = (float*)d_out;

    // Deterministic per-launch state: zero h_0 (buffer 0) + barrier counters.
    void *hhi_a = nullptr, *hlo_a = nullptr, *bar_a = nullptr;
    cudaGetSymbolAddress(&hhi_a, g_Hhi);
    cudaGetSymbolAddress(&hlo_a, g_Hlo);
    cudaGetSymbolAddress(&bar_a, g_bar);
    cudaMemsetAsync(hhi_a, 0, (size_t)B_DIM * H_DIM * sizeof(__nv_bfloat16));
    cudaMemsetAsync(hlo_a, 0, (size_t)B_DIM * H_DIM * sizeof(__nv_bfloat16));
    cudaMemsetAsync(bar_a, 0, 16 * 32 * sizeof(unsigned));

    cudaFuncSetAttribute(rnn_hmma10_kernel,
                         cudaFuncAttributeMaxDynamicSharedMemorySize, SMEM_SZ);

    rnn_hmma10_kernel<<<GRID, NTHR, SMEM_SZ>>>(x, Whx, Whh, Wph, bh, bp, out);
}

// round 11
// speedup vs baseline: 2.0480x; 1.1254x over previous
#include <cuda_runtime.h>
#include <cuda_bf16.h>
#include <cstdint>

// VanillaRNN via HMMA bf16-split (fp32 accum). B=256,T=1024,D=64,H=512,C=10.
// 128 CTAs = 16 row-tiles x 8 col-slices, 512 threads.
// R11: per-CTA K-permutation (x | own-h | remote-h) -> phase-split GEMM that
// runs k0..127 BEFORE the inter-CTA barrier; own h staged by STS from
// registers; fence-free release/acquire barrier (atom.release + ld.acquire).

#define T_SEQ  1024
#define B_DIM  256
#define D_IN   64
#define H_DIM  512
#define NCLS   10
#define KTOT   576
#define GRID   128
#define NTHR   512
#define TILE_R 16
#define TILE_C 64

#define PKB    1168            // A/B row stride bytes: 576*2 + 16 pad
#define REDW   70              // sRed row stride in floats (bank spread)

#define OFF_AH   0
#define OFF_AL   (OFF_AH + TILE_R * PKB)          // 18688
#define OFF_BH   (OFF_AL + TILE_R * PKB)          // 37376
#define OFF_BL   (OFF_BH + TILE_C * PKB)          // 112128
#define OFF_RED  (OFF_BL + TILE_C * PKB)          // 186880
#define OFF_BIAS (OFF_RED + 4 * 16 * REDW * 4)    // 204800
#define SMEM_SZ  (OFF_BIAS + 256 + 16)

__device__ __nv_bfloat16 g_xhi[(size_t)B_DIM * T_SEQ * D_IN];
__device__ __nv_bfloat16 g_xlo[(size_t)B_DIM * T_SEQ * D_IN];
__device__ __nv_bfloat16 g_Hhi[2][B_DIM][H_DIM];
__device__ __nv_bfloat16 g_Hlo[2][B_DIM][H_DIM];
__device__ float         g_hfin[B_DIM][H_DIM];
__device__ unsigned      g_bar[16 * 32];   // 1 counter per row-tile, 128B apart

__device__ __forceinline__ uint32_t smem_u32(const void* p) {
    uint32_t a;
    asm("{ .reg .u64 t; cvta.to.shared.u64 t, %1; cvt.u32.u64 %0, t; }"
        : "=r"(a) : "l"(p));
    return a;
}
__device__ __forceinline__ void bar_arrive_release(unsigned* ctr) {
    unsigned old;
    asm volatile("atom.release.gpu.add.u32 %0, [%1], 1;"
                 : "=r"(old) : "l"(ctr) : "memory");
}
__device__ __forceinline__ unsigned ld_acquire(const unsigned* p) {
    unsigned v;
    asm volatile("ld.acquire.gpu.u32 %0, [%1];" : "=r"(v) : "l"(p) : "memory");
    return v;
}

#define LDSM4(r0, r1, r2, r3, addr)                                        \
    asm volatile("ldmatrix.sync.aligned.m8n8.x4.shared.b16 "               \
                 "{%0,%1,%2,%3}, [%4];"                                    \
                 : "=r"(r0), "=r"(r1), "=r"(r2), "=r"(r3) : "r"(addr))
#define MMA16816(d, a0, a1, a2, a3, b0, b1)                                \
    asm volatile("mma.sync.aligned.m16n8k16.row.col.f32.bf16.bf16.f32 "    \
                 "{%0,%1,%2,%3}, {%4,%5,%6,%7}, {%8,%9}, {%0,%1,%2,%3};"   \
                 : "+f"(d[0]), "+f"(d[1]), "+f"(d[2]), "+f"(d[3])          \
                 : "r"(a0), "r"(a1), "r"(a2), "r"(a3), "r"(b0), "r"(b1))

__global__ void __launch_bounds__(NTHR, 1)
rnn_hmma11_kernel(const float* __restrict__ x,
                  const float* __restrict__ Whx,
                  const float* __restrict__ Whh,
                  const float* __restrict__ Wph,
                  const float* __restrict__ bh,
                  const float* __restrict__ bp,
                  float* __restrict__ out)
{
    extern __shared__ __align__(16) char smg[];
    const uint32_t sb = smem_u32(smg);

    const int tid  = threadIdx.x;
    const int wid  = tid >> 5;
    const int lane = tid & 31;
    const int bid  = blockIdx.x;
    const int jt   = bid & 7;            // col slice
    const int it   = bid >> 3;           // row tile
    const int c0   = jt * TILE_C;
    const int r0   = it * TILE_R;
    unsigned* barp = &g_bar[it * 32];

    float* sBias = reinterpret_cast<float*>(smg + OFF_BIAS);
    float* sRed  = reinterpret_cast<float*>(smg + OFF_RED);

    // ---- one-time: W slice -> SMEM bf16 hi/lo, K PERMUTED per CTA ----
    // local k: [0,64)=x rows; chunk c>=1 (k in [c*64,(c+1)*64)) = Whh rows of
    // slice (jt + c - 1) & 7. Chunk 1 == own slice.
    for (int i = tid; i < TILE_C * KTOT; i += NTHR) {
        const int n = i / KTOT, km = i - n * KTOT;
        const int c = km >> 6, kr = km & 63;
        const float w = (c == 0)
            ? Whx[km * H_DIM + c0 + n]
            : Whh[((((jt + c - 1) & 7) << 6) + kr) * H_DIM + c0 + n];
        const __nv_bfloat16 h16 = __float2bfloat16(w);
        const __nv_bfloat16 l16 = __float2bfloat16(w - __bfloat162float(h16));
        *reinterpret_cast<__nv_bfloat16*>(smg + OFF_BH + n * PKB + km * 2) = h16;
        *reinterpret_cast<__nv_bfloat16*>(smg + OFF_BL + n * PKB + km * 2) = l16;
    }
    if (tid < TILE_C) sBias[tid] = bh[c0 + tid];

    // ---- prologue: split THIS row-tile's x rows into bf16 hi/lo ----
    {
        const size_t gbase = (size_t)r0 * T_SEQ * D_IN / 4;
        const int    total = TILE_R * T_SEQ * D_IN / 4;
        for (int i = jt * NTHR + tid; i < total; i += 8 * NTHR) {
            const float4 v = __ldg(reinterpret_cast<const float4*>(x) + gbase + i);
            const __nv_bfloat162 hA = __floats2bfloat162_rn(v.x, v.y);
            const __nv_bfloat162 hB = __floats2bfloat162_rn(v.z, v.w);
            const __nv_bfloat162 lA = __floats2bfloat162_rn(
                v.x - __bfloat162float(hA.x), v.y - __bfloat162float(hA.y));
            const __nv_bfloat162 lB = __floats2bfloat162_rn(
                v.z - __bfloat162float(hB.x), v.w - __bfloat162float(hB.y));
            const size_t o = gbase + i;
            reinterpret_cast<__nv_bfloat162*>(g_xhi)[2 * o]     = hA;
            reinterpret_cast<__nv_bfloat162*>(g_xhi)[2 * o + 1] = hB;
            reinterpret_cast<__nv_bfloat162*>(g_xlo)[2 * o]     = lA;
            reinterpret_cast<__nv_bfloat162*>(g_xlo)[2 * o + 1] = lB;
        }
    }
    // prologue barrier (epoch 1): x split visible tile-wide
    __syncthreads();
    if (tid == 0) {
        bar_arrive_release(barp);
        while (ld_acquire(barp) < 8u) { }
    }
    __syncthreads();

    // warp roles
    const int kg = wid >> 2;             // K-group
    const int ng = wid & 3;              // 16-col group

    const uint32_t aoff = (uint32_t)(lane & 15) * PKB
                        + (uint32_t)((lane >> 4) << 4);
    const uint32_t boff = (uint32_t)(ng * 16 + ((lane >> 4) << 3) + (lane & 7)) * PKB
                        + (uint32_t)(((lane >> 3) & 1) << 4);

    const uint32_t sAh = sb + OFF_AH, sAl = sb + OFF_AL;
    const uint32_t sBh = sb + OFF_BH, sBl = sb + OFF_BL;

    // kstep byte offsets for this kg: phase1 = 2 steps, phase2 = 7 steps
    uint32_t kofs[9];
    kofs[0] = (uint32_t)kg * 64;
    kofs[1] = (uint32_t)kg * 64 + 32;
    #pragma unroll
    for (int j = 0; j < 7; ++j)
        kofs[2 + j] = 256u + (uint32_t)kg * 224 + (uint32_t)j * 32;

    // ---- B-hi fragments register-resident for all steps ----
    uint32_t bhr[9][4];
    #pragma unroll
    for (int s = 0; s < 9; ++s)
        LDSM4(bhr[s][0], bhr[s][1], bhr[s][2], bhr[s][3], sBh + boff + kofs[s]);

    const int erow = (tid * 2) >> 6;
    const int ecol = (tid * 2) & 63;

    // x-stage mapping (tid < 256 handles one uint4 of chunk 0)
    const int xhalf = tid >> 7;
    const int xr    = (tid & 127) >> 3;
    const int xq    = tid & 7;

    // ---- stage A for t=0: x_0 (chunk0) + zeros (chunk1 = own h_0) ----
    if (tid < 256) {
        const __nv_bfloat16* src = (xhalf ? g_xlo : g_xhi)
            + ((size_t)(r0 + xr) * T_SEQ + 0) * D_IN + xq * 8;
        *reinterpret_cast<uint4*>(smg + (xhalf ? OFF_AL : OFF_AH)
                                  + xr * PKB + xq * 16)
            = __ldg(reinterpret_cast<const uint4*>(src));
        // chunk1 zeros (k 64..127): byte 128 + q*16
        *reinterpret_cast<uint4*>(smg + (xhalf ? OFF_AL : OFF_AH)
                                  + xr * PKB + 128 + xq * 16)
            = make_uint4(0, 0, 0, 0);
    }
    __syncthreads();

    for (int t = 0; t < T_SEQ; ++t) {
        // ---- phase 1: k 0..127 (x + own h) -- no barrier needed ----
        float acc[2][4] = {};
        #pragma unroll
        for (int s = 0; s < 2; ++s) {
            const uint32_t ka = kofs[s];
            uint32_t ah0, ah1, ah2, ah3, al0, al1, al2, al3;
            uint32_t bl0, bl1, bl2, bl3;
            LDSM4(ah0, ah1, ah2, ah3, sAh + aoff + ka);
            LDSM4(al0, al1, al2, al3, sAl + aoff + ka);
            LDSM4(bl0, bl1, bl2, bl3, sBl + boff + ka);
            MMA16816(acc[0], ah0, ah1, ah2, ah3, bhr[s][0], bhr[s][1]);
            MMA16816(acc[0], al0, al1, al2, al3, bhr[s][0], bhr[s][1]);
            MMA16816(acc[0], ah0, ah1, ah2, ah3, bl0, bl1);
            MMA16816(acc[1], ah0, ah1, ah2, ah3, bhr[s][2], bhr[s][3]);
            MMA16816(acc[1], al0, al1, al2, al3, bhr[s][2], bhr[s][3]);
            MMA16816(acc[1], ah0, ah1, ah2, ah3, bl2, bl3);
        }

        // ---- barrier wait: remote h(t) published? (epoch t+1) ----
        if (tid == 0) {
            const unsigned target = 8u * (unsigned)(t + 1);
            while (ld_acquire(barp) < target) { }
        }
        __syncthreads();

        // ---- stage remote h(t): 7 slices -> chunks 2..8 ----
        {
            const __nv_bfloat16* hbh = &g_Hhi[t & 1][0][0];
            const __nv_bfloat16* hbl = &g_Hlo[t & 1][0][0];
            for (int u = tid; u < 1792; u += NTHR) {
                const int half = u >= 896;
                const int uu = half ? u - 896 : u;
                const int si = uu >> 7;           // 0..6
                const int rem = uu & 127;
                const int r = rem >> 3, q = rem & 7;
                const int jr = (jt + 1 + si) & 7;
                const __nv_bfloat16* src = (half ? hbl : hbh)
                    + (size_t)(r0 + r) * H_DIM + jr * 64 + q * 8;
                *reinterpret_cast<uint4*>(smg + (half ? OFF_AL : OFF_AH)
                                          + r * PKB + 256 + si * 128 + q * 16)
                    = __ldcv(reinterpret_cast<const uint4*>(src));
            }
        }
        __syncthreads();

        // ---- phase 2: k 128..575 (remote h) ----
        #pragma unroll
        for (int s = 2; s < 9; ++s) {
            const uint32_t ka = kofs[s];
            uint32_t ah0, ah1, ah2, ah3, al0, al1, al2, al3;
            uint32_t bl0, bl1, bl2, bl3;
            LDSM4(ah0, ah1, ah2, ah3, sAh + aoff + ka);
            LDSM4(al0, al1, al2, al3, sAl + aoff + ka);
            LDSM4(bl0, bl1, bl2, bl3, sBl + boff + ka);
            MMA16816(acc[0], ah0, ah1, ah2, ah3, bhr[s][0], bhr[s][1]);
            MMA16816(acc[0], al0, al1, al2, al3, bhr[s][0], bhr[s][1]);
            MMA16816(acc[0], ah0, ah1, ah2, ah3, bl0, bl1);
            MMA16816(acc[1], ah0, ah1, ah2, ah3, bhr[s][2], bhr[s][3]);
            MMA16816(acc[1], al0, al1, al2, al3, bhr[s][2], bhr[s][3]);
            MMA16816(acc[1], ah0, ah1, ah2, ah3, bl2, bl3);
        }

        // ---- split-K partials -> sRed (bank-spread) ----
        {
            float* rb = sRed + kg * (16 * REDW);
            const int gr0 = lane >> 2;
            #pragma unroll
            for (int g = 0; g < 2; ++g) {
                const int c = ng * 16 + g * 8 + (lane & 3) * 2;
                *reinterpret_cast<float2*>(rb + gr0 * REDW + c) =
                    make_float2(acc[g][0], acc[g][1]);
                *reinterpret_cast<float2*>(rb + (gr0 + 8) * REDW + c) =
                    make_float2(acc[g][2], acc[g][3]);
            }
        }
        __syncthreads();

        // ---- issue x_{t+1} LDG (flies over the reduce) ----
        uint4 xv;
        const bool do_x = (t + 1 < T_SEQ) && (tid < 256);
        if (do_x) {
            const __nv_bfloat16* src = (xhalf ? g_xlo : g_xhi)
                + ((size_t)(r0 + xr) * T_SEQ + (t + 1)) * D_IN + xq * 8;
            xv = __ldg(reinterpret_cast<const uint4*>(src));
        }

        // ---- reduce + bias + tanh; publish h(t+1); STS own h + x ----
        {
            const int base = erow * REDW + ecol;
            float2 p0 = *reinterpret_cast<float2*>(sRed + base);
            float2 p1 = *reinterpret_cast<float2*>(sRed + 16 * REDW + base);
            float2 p2 = *reinterpret_cast<float2*>(sRed + 32 * REDW + base);
            float2 p3 = *reinterpret_cast<float2*>(sRed + 48 * REDW + base);
            const float v0 = tanhf((p0.x + p1.x) + (p2.x + p3.x) + sBias[ecol]);
            const float v1 = tanhf((p0.y + p1.y) + (p2.y + p3.y) + sBias[ecol + 1]);

            const __nv_bfloat162 h01 = __floats2bfloat162_rn(v0, v1);
            const __nv_bfloat162 l01 = __floats2bfloat162_rn(
                v0 - __bfloat162float(h01.x), v1 - __bfloat162float(h01.y));

            // global (for peers)
            const int row = r0 + erow, col = c0 + ecol;
            *reinterpret_cast<uint32_t*>(&g_Hhi[(t + 1) & 1][row][col]) =
                *reinterpret_cast<const uint32_t*>(&h01);
            *reinterpret_cast<uint32_t*>(&g_Hlo[(t + 1) & 1][row][col]) =
                *reinterpret_cast<const uint32_t*>(&l01);
            if (t == T_SEQ - 1)
                *reinterpret_cast<float2*>(&g_hfin[row][col]) =
                    make_float2(v0, v1);

            // own h -> A chunk 1 (k = 64 + ecol), both halves
            *reinterpret_cast<uint32_t*>(smg + OFF_AH + erow * PKB
                                         + (64 + ecol) * 2) =
                *reinterpret_cast<const uint32_t*>(&h01);
            *reinterpret_cast<uint32_t*>(smg + OFF_AL + erow * PKB
                                         + (64 + ecol) * 2) =
                *reinterpret_cast<const uint32_t*>(&l01);
        }
        if (do_x) {
            *reinterpret_cast<uint4*>(smg + (xhalf ? OFF_AL : OFF_AH)
                                      + xr * PKB + xq * 16) = xv;
        }

        __syncthreads();   // chunks 0-1 consistent; all h STGs issued
        if (tid == 0) bar_arrive_release(barp);   // epoch t+2
    }

    // ---- final projection p = h_final @ Wph + bp (col-slice-0 CTAs) ----
    if (jt == 0) {
        float* sW = reinterpret_cast<float*>(smg + OFF_BH);   // 5120 floats
        float* sH = reinterpret_cast<float*>(smg + OFF_AH);   // 16x512
        for (int i = tid; i < H_DIM * NCLS; i += NTHR)
            sW[i] = Wph[i];
        for (int i = tid; i < TILE_R * H_DIM; i += NTHR) {
            const int r = i >> 9, k = i & 511;
            sH[r * H_DIM + k] = __ldcv(&g_hfin[r0 + r][k]);
        }
        __syncthreads();
        for (int i = tid; i < TILE_R * NCLS; i += NTHR) {
            const int r = i / NCLS, cc = i - (i / NCLS) * NCLS;
            float s = bp[cc];
            const float* hr = sH + r * H_DIM;
            #pragma unroll 8
            for (int k = 0; k < H_DIM; ++k)
                s += hr[k] * sW[k * NCLS + cc];
            out[(r0 + r) * NCLS + cc] = s;
        }
    }
}

extern "C" void kernel_launch(void* const* d_in, const int* in_sizes, int n_in,
                              void* d_out, int out_size)
{
    const float* x   = (const float*)d_in[0];
    const float* Whx = (const float*)d_in[1];
    const float* Whh = (const float*)d_in[2];
    const float* Wph = (const float*)d_in[3];
    const float* bh  = (const float*)d_in[4];
    const float* bp  = (const float*)d_in[5];
    float* out = (float*)d_out;

    // Deterministic per-launch state: zero h_0 (buffer 0) + barrier counters.
    void *hhi_a = nullptr, *hlo_a = nullptr, *bar_a = nullptr;
    cudaGetSymbolAddress(&hhi_a, g_Hhi);
    cudaGetSymbolAddress(&hlo_a, g_Hlo);
    cudaGetSymbolAddress(&bar_a, g_bar);
    cudaMemsetAsync(hhi_a, 0, (size_t)B_DIM * H_DIM * sizeof(__nv_bfloat16));
    cudaMemsetAsync(hlo_a, 0, (size_t)B_DIM * H_DIM * sizeof(__nv_bfloat16));
    cudaMemsetAsync(bar_a, 0, 16 * 32 * sizeof(unsigned));

    cudaFuncSetAttribute(rnn_hmma11_kernel,
                         cudaFuncAttributeMaxDynamicSharedMemorySize, SMEM_SZ);

    rnn_hmma11_kernel<<<GRID, NTHR, SMEM_SZ>>>(x, Whx, Whh, Wph, bh, bp, out);
}

// round 13
// speedup vs baseline: 2.2727x; 1.1097x over previous
#include <cuda_runtime.h>
#include <cuda_bf16.h>
#include <cstdint>

// VanillaRNN via HMMA bf16-split (fp32 accum). B=256,T=1024,D=64,H=512,C=10.
// 128 CTAs = 16 row-tiles x 8 col-slices. 544 threads = 16 worker warps
// (4 K-groups x 4 col-groups) + 1 poll warp.
// R13 (= R12 fixed): remote-h staging grouped BY SLICE -- grp1 = slices 0-2
// (hi+lo) feeds MMA steps 2-4; grp2 = slices 3-6 (hi+lo) feeds steps 5-8.
// Poll warp overlaps the barrier poll with phase-1 MMA.

#define T_SEQ  1024
#define B_DIM  256
#define D_IN   64
#define H_DIM  512
#define NCLS   10
#define KTOT   576
#define GRID   128
#define NTHR   544
#define NWRK   512
#define TILE_R 16
#define TILE_C 64

#define PKB    1168            // A/B row stride bytes: 576*2 + 16 pad
#define REDW   70              // sRed row stride in floats (bank spread)

#define OFF_AH   0
#define OFF_AL   (OFF_AH + TILE_R * PKB)          // 18688
#define OFF_BH   (OFF_AL + TILE_R * PKB)          // 37376
#define OFF_BL   (OFF_BH + TILE_C * PKB)          // 112128
#define OFF_RED  (OFF_BL + TILE_C * PKB)          // 186880
#define OFF_BIAS (OFF_RED + 4 * 16 * REDW * 4)    // 204800
#define SMEM_SZ  (OFF_BIAS + 256 + 16)

__device__ __nv_bfloat16 g_xhi[(size_t)B_DIM * T_SEQ * D_IN];
__device__ __nv_bfloat16 g_xlo[(size_t)B_DIM * T_SEQ * D_IN];
__device__ __nv_bfloat16 g_Hhi[2][B_DIM][H_DIM];
__device__ __nv_bfloat16 g_Hlo[2][B_DIM][H_DIM];
__device__ float         g_hfin[B_DIM][H_DIM];
__device__ unsigned      g_bar[16 * 32];   // 1 counter per row-tile, 128B apart

__device__ __forceinline__ uint32_t smem_u32(const void* p) {
    uint32_t a;
    asm("{ .reg .u64 t; cvta.to.shared.u64 t, %1; cvt.u32.u64 %0, t; }"
        : "=r"(a) : "l"(p));
    return a;
}
__device__ __forceinline__ void bar_arrive_release(unsigned* ctr) {
    unsigned old;
    asm volatile("atom.release.gpu.add.u32 %0, [%1], 1;"
                 : "=r"(old) : "l"(ctr) : "memory");
}
__device__ __forceinline__ unsigned ld_acquire(const unsigned* p) {
    unsigned v;
    asm volatile("ld.acquire.gpu.u32 %0, [%1];" : "=r"(v) : "l"(p) : "memory");
    return v;
}

#define LDSM4(r0, r1, r2, r3, addr)                                        \
    asm volatile("ldmatrix.sync.aligned.m8n8.x4.shared.b16 "               \
                 "{%0,%1,%2,%3}, [%4];"                                    \
                 : "=r"(r0), "=r"(r1), "=r"(r2), "=r"(r3) : "r"(addr))
#define MMA16816(d, a0, a1, a2, a3, b0, b1)                                \
    asm volatile("mma.sync.aligned.m16n8k16.row.col.f32.bf16.bf16.f32 "    \
                 "{%0,%1,%2,%3}, {%4,%5,%6,%7}, {%8,%9}, {%0,%1,%2,%3};"   \
                 : "+f"(d[0]), "+f"(d[1]), "+f"(d[2]), "+f"(d[3])          \
                 : "r"(a0), "r"(a1), "r"(a2), "r"(a3), "r"(b0), "r"(b1))

#define STEP_BODY(s)                                                       \
    do {                                                                   \
        const uint32_t ka = kofs[s];                                       \
        uint32_t ah0, ah1, ah2, ah3, al0, al1, al2, al3;                   \
        uint32_t bl0, bl1, bl2, bl3;                                       \
        LDSM4(ah0, ah1, ah2, ah3, sAh + aoff + ka);                        \
        LDSM4(al0, al1, al2, al3, sAl + aoff + ka);                        \
        LDSM4(bl0, bl1, bl2, bl3, sBl + boff + ka);                        \
        MMA16816(acc[0], ah0, ah1, ah2, ah3, bhr[s][0], bhr[s][1]);        \
        MMA16816(acc[0], al0, al1, al2, al3, bhr[s][0], bhr[s][1]);        \
        MMA16816(acc[0], ah0, ah1, ah2, ah3, bl0, bl1);                    \
        MMA16816(acc[1], ah0, ah1, ah2, ah3, bhr[s][2], bhr[s][3]);        \
        MMA16816(acc[1], al0, al1, al2, al3, bhr[s][2], bhr[s][3]);        \
        MMA16816(acc[1], ah0, ah1, ah2, ah3, bl2, bl3);                    \
    } while (0)

__global__ void __launch_bounds__(NTHR, 1)
rnn_hmma13_kernel(const float* __restrict__ x,
                  const float* __restrict__ Whx,
                  const float* __restrict__ Whh,
                  const float* __restrict__ Wph,
                  const float* __restrict__ bh,
                  const float* __restrict__ bp,
                  float* __restrict__ out)
{
    extern __shared__ __align__(16) char smg[];
    const uint32_t sb = smem_u32(smg);

    const int tid  = threadIdx.x;
    const int wid  = tid >> 5;
    const int lane = tid & 31;
    const int bid  = blockIdx.x;
    const int jt   = bid & 7;            // col slice
    const int it   = bid >> 3;           // row tile
    const int c0   = jt * TILE_C;
    const int r0   = it * TILE_R;
    const bool wrk = (tid < NWRK);
    unsigned* barp = &g_bar[it * 32];

    float* sBias = reinterpret_cast<float*>(smg + OFF_BIAS);
    float* sRed  = reinterpret_cast<float*>(smg + OFF_RED);

    // ---- one-time: W slice -> SMEM bf16 hi/lo, K PERMUTED per CTA ----
    // local k: [0,64)=x; chunk c>=1 = Whh rows of slice (jt+c-1)&7.
    for (int i = tid; i < TILE_C * KTOT; i += NTHR) {
        const int n = i / KTOT, km = i - n * KTOT;
        const int c = km >> 6, kr = km & 63;
        const float w = (c == 0)
            ? Whx[km * H_DIM + c0 + n]
            : Whh[((((jt + c - 1) & 7) << 6) + kr) * H_DIM + c0 + n];
        const __nv_bfloat16 h16 = __float2bfloat16(w);
        const __nv_bfloat16 l16 = __float2bfloat16(w - __bfloat162float(h16));
        *reinterpret_cast<__nv_bfloat16*>(smg + OFF_BH + n * PKB + km * 2) = h16;
        *reinterpret_cast<__nv_bfloat16*>(smg + OFF_BL + n * PKB + km * 2) = l16;
    }
    if (tid < TILE_C) sBias[tid] = bh[c0 + tid];

    // ---- prologue: split THIS row-tile's x rows into bf16 hi/lo ----
    {
        const size_t gbase = (size_t)r0 * T_SEQ * D_IN / 4;
        const int    total = TILE_R * T_SEQ * D_IN / 4;
        for (int i = jt * NTHR + tid; i < total; i += 8 * NTHR) {
            const float4 v = __ldg(reinterpret_cast<const float4*>(x) + gbase + i);
            const __nv_bfloat162 hA = __floats2bfloat162_rn(v.x, v.y);
            const __nv_bfloat162 hB = __floats2bfloat162_rn(v.z, v.w);
            const __nv_bfloat162 lA = __floats2bfloat162_rn(
                v.x - __bfloat162float(hA.x), v.y - __bfloat162float(hA.y));
            const __nv_bfloat162 lB = __floats2bfloat162_rn(
                v.z - __bfloat162float(hB.x), v.w - __bfloat162float(hB.y));
            const size_t o = gbase + i;
            reinterpret_cast<__nv_bfloat162*>(g_xhi)[2 * o]     = hA;
            reinterpret_cast<__nv_bfloat162*>(g_xhi)[2 * o + 1] = hB;
            reinterpret_cast<__nv_bfloat162*>(g_xlo)[2 * o]     = lA;
            reinterpret_cast<__nv_bfloat162*>(g_xlo)[2 * o + 1] = lB;
        }
    }
    __syncthreads();
    if (tid == NWRK) {           // poll warp leader: prologue barrier (epoch 1)
        bar_arrive_release(barp);
        while (ld_acquire(barp) < 8u) { }
    }
    __syncthreads();

    // worker warp roles
    const int kg = wid >> 2;
    const int ng = wid & 3;

    const uint32_t aoff = (uint32_t)(lane & 15) * PKB
                        + (uint32_t)((lane >> 4) << 4);
    const uint32_t boff = (uint32_t)(ng * 16 + ((lane >> 4) << 3) + (lane & 7)) * PKB
                        + (uint32_t)(((lane >> 3) & 1) << 4);

    const uint32_t sAh = sb + OFF_AH, sAl = sb + OFF_AL;
    const uint32_t sBh = sb + OFF_BH, sBl = sb + OFF_BL;

    // k-step byte offsets: phase1 s=0,1 (chunks 0-1); phase2 s=2..8
    // interleaved across kg: k = 128 + (kg + 4*(s-2))*16
    //   steps 2-4 -> k in [128,320) = slices 0-2 ; steps 5-8 -> slices 3-6
    uint32_t kofs[9];
    kofs[0] = (uint32_t)kg * 64;
    kofs[1] = (uint32_t)kg * 64 + 32;
    #pragma unroll
    for (int j = 0; j < 7; ++j)
        kofs[2 + j] = 256u + ((uint32_t)kg + 4u * j) * 32u;

    // ---- B-hi fragments register-resident ----
    uint32_t bhr[9][4];
    if (wrk) {
        #pragma unroll
        for (int s = 0; s < 9; ++s)
            LDSM4(bhr[s][0], bhr[s][1], bhr[s][2], bhr[s][3],
                  sBh + boff + kofs[s]);
    }

    const int erow = (tid * 2) >> 6;
    const int ecol = (tid * 2) & 63;

    // ---- remote-h staging, grouped BY SLICE (t-invariant precompute) ----
    // grp1: slices 0-2, both halves: 768 units. unit g: half=g/384,
    //   gg=g%384, si=gg>>7, rem=gg&127, r=rem>>3, q=rem&7.
    //   assignment: g=tid (all 512 workers), g=512+tid (tid<256).
    // grp2: slices 3-6, both halves: 1024 units. unit g: half=g/512,
    //   gg=g&511, si=3+(gg>>7). assignment: g=tid, g=512+tid (all workers).
    int      p1src[2]; uint32_t p1dst[2]; bool p1half[2];
    int      p2src[2]; uint32_t p2dst[2]; bool p2half[2];
    {
        #pragma unroll
        for (int j = 0; j < 2; ++j) {
            // grp1
            {
                const int g = j * NWRK + (wrk ? tid : 0);
                const int gc = (g < 768) ? g : 0;          // clamp (unused lanes)
                const bool half = gc >= 384;
                const int gg = half ? gc - 384 : gc;
                const int si = gg >> 7, rem = gg & 127, r = rem >> 3, q = rem & 7;
                const int jr = (jt + 1 + si) & 7;
                p1half[j] = half;
                p1src[j]  = (r0 + r) * H_DIM + jr * 64 + q * 8;
                p1dst[j]  = (half ? OFF_AL : OFF_AH) + r * PKB
                          + 256 + si * 128 + q * 16;
            }
            // grp2
            {
                const int g = j * NWRK + (wrk ? tid : 0);
                const bool half = g >= 512;
                const int gg = g & 511;
                const int si = 3 + (gg >> 7), rem = gg & 127,
                          r = rem >> 3, q = rem & 7;
                const int jr = (jt + 1 + si) & 7;
                p2half[j] = half;
                p2src[j]  = (r0 + r) * H_DIM + jr * 64 + q * 8;
                p2dst[j]  = (half ? OFF_AL : OFF_AH) + r * PKB
                          + 256 + si * 128 + q * 16;
            }
        }
    }
    const bool do_p1b = wrk && (tid < 256);    // grp1 second unit

    // x-stage t-invariant pieces (tid < 256)
    const int xhalf = tid >> 7;
    const int xr    = (tid & 127) >> 3;
    const int xq    = tid & 7;
    const size_t xsrc0 = (size_t)(r0 + xr) * T_SEQ * D_IN + xq * 8;
    const uint32_t xdst = (xhalf ? OFF_AL : OFF_AH) + xr * PKB + xq * 16;

    // ---- stage A for t=0: x_0 (chunk0) + zeros (chunk1 = own h_0) ----
    if (tid < 256) {
        const __nv_bfloat16* src = (xhalf ? g_xlo : g_xhi) + xsrc0;
        *reinterpret_cast<uint4*>(smg + xdst)
            = __ldg(reinterpret_cast<const uint4*>(src));
        *reinterpret_cast<uint4*>(smg + (xhalf ? OFF_AL : OFF_AH)
                                  + xr * PKB + 128 + xq * 16)
            = make_uint4(0, 0, 0, 0);
    }
    __syncthreads();

    for (int t = 0; t < T_SEQ; ++t) {
        float acc[2][4] = {};

        // ---- phase 1 (workers) || barrier poll (poll warp) ----
        if (wrk) {
            STEP_BODY(0);
            STEP_BODY(1);
        } else if (tid == NWRK) {
            const unsigned target = 8u * (unsigned)(t + 1);
            while (ld_acquire(barp) < target) { }
        }
        __syncthreads();   // #1: remote h(t) visible

        // ---- stage grp1 (slices 0-2, both halves) ----
        const __nv_bfloat16* hbh = &g_Hhi[t & 1][0][0];
        const __nv_bfloat16* hbl = &g_Hlo[t & 1][0][0];
        if (wrk) {
            const uint4 a = __ldcv(reinterpret_cast<const uint4*>(
                (p1half[0] ? hbl : hbh) + p1src[0]));
            uint4 b;
            if (do_p1b)
                b = __ldcv(reinterpret_cast<const uint4*>(
                    (p1half[1] ? hbl : hbh) + p1src[1]));
            *reinterpret_cast<uint4*>(smg + p1dst[0]) = a;
            if (do_p1b)
                *reinterpret_cast<uint4*>(smg + p1dst[1]) = b;
        }
        __syncthreads();   // #2: grp1 staged

        if (wrk) {
            // issue grp2 loads; MMA steps 2-4 (slices 0-2) while they fly;
            // grp2 stores hit slices 3-6 regions only (disjoint from readers)
            const uint4 a = __ldcv(reinterpret_cast<const uint4*>(
                (p2half[0] ? hbl : hbh) + p2src[0]));
            const uint4 b = __ldcv(reinterpret_cast<const uint4*>(
                (p2half[1] ? hbl : hbh) + p2src[1]));
            STEP_BODY(2);
            STEP_BODY(3);
            STEP_BODY(4);
            *reinterpret_cast<uint4*>(smg + p2dst[0]) = a;
            *reinterpret_cast<uint4*>(smg + p2dst[1]) = b;
        }
        __syncthreads();   // #3: grp2 staged

        if (wrk) {
            STEP_BODY(5);
            STEP_BODY(6);
            STEP_BODY(7);
            STEP_BODY(8);

            // split-K partials -> sRed (bank-spread)
            float* rb = sRed + kg * (16 * REDW);
            const int gr0 = lane >> 2;
            #pragma unroll
            for (int g = 0; g < 2; ++g) {
                const int c = ng * 16 + g * 8 + (lane & 3) * 2;
                *reinterpret_cast<float2*>(rb + gr0 * REDW + c) =
                    make_float2(acc[g][0], acc[g][1]);
                *reinterpret_cast<float2*>(rb + (gr0 + 8) * REDW + c) =
                    make_float2(acc[g][2], acc[g][3]);
            }
        }
        __syncthreads();   // #4: partials ready

        if (wrk) {
            // x_{t+1} LDG first (flies over the reduce)
            uint4 xv;
            const bool do_x = (t + 1 < T_SEQ) && (tid < 256);
            if (do_x) {
                const __nv_bfloat16* src = (xhalf ? g_xlo : g_xhi)
                    + xsrc0 + (size_t)(t + 1) * D_IN;
                xv = __ldg(reinterpret_cast<const uint4*>(src));
            }

            // reduce + bias + tanh; publish h(t+1); STS own h
            {
                const int base = erow * REDW + ecol;
                float2 p0 = *reinterpret_cast<float2*>(sRed + base);
                float2 p1 = *reinterpret_cast<float2*>(sRed + 16 * REDW + base);
                float2 p2 = *reinterpret_cast<float2*>(sRed + 32 * REDW + base);
                float2 p3 = *reinterpret_cast<float2*>(sRed + 48 * REDW + base);
                const float v0 = tanhf((p0.x + p1.x) + (p2.x + p3.x) + sBias[ecol]);
                const float v1 = tanhf((p0.y + p1.y) + (p2.y + p3.y) + sBias[ecol + 1]);

                const __nv_bfloat162 h01 = __floats2bfloat162_rn(v0, v1);
                const __nv_bfloat162 l01 = __floats2bfloat162_rn(
                    v0 - __bfloat162float(h01.x), v1 - __bfloat162float(h01.y));

                const int row = r0 + erow, col = c0 + ecol;
                *reinterpret_cast<uint32_t*>(&g_Hhi[(t + 1) & 1][row][col]) =
                    *reinterpret_cast<const uint32_t*>(&h01);
                *reinterpret_cast<uint32_t*>(&g_Hlo[(t + 1) & 1][row][col]) =
                    *reinterpret_cast<const uint32_t*>(&l01);
                if (t == T_SEQ - 1)
                    *reinterpret_cast<float2*>(&g_hfin[row][col]) =
                        make_float2(v0, v1);

                *reinterpret_cast<uint32_t*>(smg + OFF_AH + erow * PKB
                                             + (64 + ecol) * 2) =
                    *reinterpret_cast<const uint32_t*>(&h01);
                *reinterpret_cast<uint32_t*>(smg + OFF_AL + erow * PKB
                                             + (64 + ecol) * 2) =
                    *reinterpret_cast<const uint32_t*>(&l01);
            }
            if (do_x) *reinterpret_cast<uint4*>(smg + xdst) = xv;
        }
        __syncthreads();   // #5: publish issued; chunks 0-1 consistent
        if (tid == NWRK) bar_arrive_release(barp);   // epoch t+2
    }

    // ---- final projection p = h_final @ Wph + bp (col-slice-0 CTAs) ----
    if (jt == 0) {
        // wait for ALL peers' final epoch (g_hfin fully written)
        if (tid == 0) {
            while (ld_acquire(barp) < 8u * (unsigned)(T_SEQ + 1)) { }
        }
        __syncthreads();

        float* sW = reinterpret_cast<float*>(smg + OFF_BH);   // 5120 floats
        float* sH = reinterpret_cast<float*>(smg + OFF_AH);   // 16x512
        for (int i = tid; i < H_DIM * NCLS; i += NTHR)
            sW[i] = Wph[i];
        for (int i = tid; i < TILE_R * H_DIM; i += NTHR) {
            const int r = i >> 9, k = i & 511;
            sH[r * H_DIM + k] = __ldcv(&g_hfin[r0 + r][k]);
        }
        __syncthreads();
        for (int i = tid; i < TILE_R * NCLS; i += NTHR) {
            const int r = i / NCLS, cc = i - (i / NCLS) * NCLS;
            float s = bp[cc];
            const float* hr = sH + r * H_DIM;
            #pragma unroll 8
            for (int k = 0; k < H_DIM; ++k)
                s += hr[k] * sW[k * NCLS + cc];
            out[(r0 + r) * NCLS + cc] = s;
        }
    }
}

extern "C" void kernel_launch(void* const* d_in, const int* in_sizes, int n_in,
                              void* d_out, int out_size)
{
    const float* x   = (const float*)d_in[0];
    const float* Whx = (const float*)d_in[1];
    const float* Whh = (const float*)d_in[2];
    const float* Wph = (const float*)d_in[3];
    const float* bh  = (const float*)d_in[4];
    const float* bp  = (const float*)d_in[5];
    float* out = (float*)d_out;

    // Deterministic per-launch state: zero h_0 (buffer 0) + barrier counters.
    void *hhi_a = nullptr, *hlo_a = nullptr, *bar_a = nullptr;
    cudaGetSymbolAddress(&hhi_a, g_Hhi);
    cudaGetSymbolAddress(&hlo_a, g_Hlo);
    cudaGetSymbolAddress(&bar_a, g_bar);
    cudaMemsetAsync(hhi_a, 0, (size_t)B_DIM * H_DIM * sizeof(__nv_bfloat16));
    cudaMemsetAsync(hlo_a, 0, (size_t)B_DIM * H_DIM * sizeof(__nv_bfloat16));
    cudaMemsetAsync(bar_a, 0, 16 * 32 * sizeof(unsigned));

    cudaFuncSetAttribute(rnn_hmma13_kernel,
                         cudaFuncAttributeMaxDynamicSharedMemorySize, SMEM_SZ);

    rnn_hmma13_kernel<<<GRID, NTHR, SMEM_SZ>>>(x, Whx, Whh, Wph, bh, bp, out);
}